// round 7
// baseline (speedup 1.0000x reference)
#include <cuda_runtime.h>
#include <cuda_bf16.h>
#include <cstdint>
#include <math.h>

#define Bz 4
#define Cc 256
#define Nn 4096
#define BM 64
#define BN 128
#define NSTEP (Nn / BN)   // 32

// ---------------- device scratch -------------------------------------------
__device__ __nv_bfloat16 g_Qt[(size_t)Bz * Nn * Cc];  // Q^T  [b][i][c]
__device__ __nv_bfloat16 g_Kt[(size_t)Bz * Nn * Cc];  // K^T  [b][j][c]
__device__ __nv_bfloat16 g_Vb[(size_t)Bz * Cc * Nn];  // V    [b][c][j]
__device__ __nv_bfloat16 g_Xt[(size_t)Bz * Nn * Cc];  // x^T  [b][n][c] bf16
__device__ __nv_bfloat16 g_Wb[3 * Cc * Cc];           // W bf16 [m][o][c]

// ---------------- PTX helpers (plain sm_103-safe) ---------------------------
__device__ __forceinline__ uint32_t smem_u32(const void* p) {
    uint32_t a;
    asm("{ .reg .u64 t; cvta.to.shared.u64 t, %1; cvt.u32.u64 %0, t; }"
        : "=r"(a) : "l"(p));
    return a;
}
__device__ __forceinline__ void ldsm4(uint32_t* r, uint32_t a) {
    asm volatile("ldmatrix.sync.aligned.m8n8.x4.shared.b16 {%0,%1,%2,%3}, [%4];"
                 : "=r"(r[0]), "=r"(r[1]), "=r"(r[2]), "=r"(r[3]) : "r"(a));
}
__device__ __forceinline__ void mma16816(float* c, const uint32_t* a,
                                         uint32_t b0, uint32_t b1) {
    asm volatile(
        "mma.sync.aligned.m16n8k16.row.col.f32.bf16.bf16.f32 "
        "{%0,%1,%2,%3}, {%4,%5,%6,%7}, {%8,%9}, {%0,%1,%2,%3};"
        : "+f"(c[0]), "+f"(c[1]), "+f"(c[2]), "+f"(c[3])
        : "r"(a[0]), "r"(a[1]), "r"(a[2]), "r"(a[3]), "r"(b0), "r"(b1));
}
#define CP_ASYNC16(dst, src) \
    asm volatile("cp.async.cg.shared.global [%0], [%1], 16;" :: "r"(dst), "l"(src))
#define CP_COMMIT() asm volatile("cp.async.commit_group;" ::: "memory")
#define CP_WAIT1()  asm volatile("cp.async.wait_group 1;" ::: "memory")

#define SQK 264
#define SVP 136
#define OFF_Q 0
#define OFF_K (64 * SQK)
#define OFF_V (OFF_K + 128 * SQK)
#define OFF_P (OFF_V + 256 * SVP)
#define SMEM_BYTES ((OFF_P + 64 * SVP) * 2)   // 188416 B

// ---------------------------------------------------------------------------
// Prep A: W fp32 -> bf16
// grid (64, 3), block 256
// ---------------------------------------------------------------------------
__global__ __launch_bounds__(256) void wconv_kernel(
    const float* __restrict__ Wq, const float* __restrict__ Wk,
    const float* __restrict__ Wv)
{
    int m = blockIdx.y;
    const float* W = (m == 0) ? Wq : (m == 1) ? Wk : Wv;
    int idx = (blockIdx.x * 256 + threadIdx.x) * 4;
    float4 v = *(const float4*)&W[idx];
    __nv_bfloat162 p[2];
    p[0] = __floats2bfloat162_rn(v.x, v.y);
    p[1] = __floats2bfloat162_rn(v.z, v.w);
    *(uint2*)&g_Wb[m * Cc * Cc + idx] = *(uint2*)p;
}

// ---------------------------------------------------------------------------
// Prep B: transpose-convert x [b][c][n] fp32 -> Xt [b][n][c] bf16
// grid (Nn/32, Cc/32, Bz), block 256 (32x8)
// ---------------------------------------------------------------------------
__global__ __launch_bounds__(256) void xpose_kernel(const float* __restrict__ x)
{
    __shared__ float tile[32][33];
    int b = blockIdx.z;
    int c0 = blockIdx.y * 32, n0 = blockIdx.x * 32;
    int tx = threadIdx.x & 31, ty = threadIdx.x >> 5;
    #pragma unroll
    for (int s = 0; s < 4; ++s)
        tile[ty + s * 8][tx] = x[((size_t)b * Cc + c0 + ty + s * 8) * Nn + n0 + tx];
    __syncthreads();
    #pragma unroll
    for (int s = 0; s < 4; ++s)
        g_Xt[((size_t)b * Nn + n0 + ty + s * 8) * Cc + c0 + tx] =
            __float2bfloat16(tile[tx][ty + s * 8]);
}

// ---------------------------------------------------------------------------
// Shared HMMA GEMM core (round-4, validated): C[128x128] = A[128xK] B[128xK]^T
// ---------------------------------------------------------------------------
#define LDS 40

template<int LDGA, int LDGB, int KT>
__device__ __forceinline__ void gemm_bf16(
    const __nv_bfloat16* __restrict__ Ag,
    const __nv_bfloat16* __restrict__ Bg,
    float acc[4][4][4])
{
    __shared__ alignas(16) __nv_bfloat16 Asm[2][128 * LDS];
    __shared__ alignas(16) __nv_bfloat16 Bsm[2][128 * LDS];

    const int tid = threadIdx.x;
    const int lane = tid & 31, wid = tid >> 5;
    const int wm = wid & 1, wn = wid >> 1;
    const int r0 = tid >> 2, cb = tid & 3;

    auto load_tile = [&](int s, int kt) {
        int k0 = kt * 32;
        #pragma unroll
        for (int h = 0; h < 2; ++h) {
            int r = r0 + h * 64;
            CP_ASYNC16(smem_u32(&Asm[s][r * LDS + cb * 8]),
                       Ag + (size_t)r * LDGA + k0 + cb * 8);
            CP_ASYNC16(smem_u32(&Bsm[s][r * LDS + cb * 8]),
                       Bg + (size_t)r * LDGB + k0 + cb * 8);
        }
        CP_COMMIT();
    };

    const int a_row = wm * 64 + (lane & 15);
    const int a_koff = (lane >> 4) * 8;
    const int b_row = wn * 32 + (lane & 7) + ((lane >> 4) << 3);
    const int b_koff = ((lane >> 3) & 1) * 8;

    load_tile(0, 0);

    #pragma unroll 1
    for (int kt = 0; kt < KT; ++kt) {
        if (kt + 1 < KT) {
            load_tile((kt + 1) & 1, kt + 1);
            asm volatile("cp.async.wait_group 1;" ::: "memory");
        } else {
            asm volatile("cp.async.wait_group 0;" ::: "memory");
        }
        __syncthreads();

        const __nv_bfloat16* as = &Asm[kt & 1][0];
        const __nv_bfloat16* bs = &Bsm[kt & 1][0];

        #pragma unroll
        for (int ks = 0; ks < 2; ++ks) {
            int k0 = ks * 16;
            uint32_t af[4][4], bf[2][4];
            #pragma unroll
            for (int mi = 0; mi < 4; ++mi)
                ldsm4(af[mi], smem_u32(as + (a_row + mi * 16) * LDS + k0 + a_koff));
            #pragma unroll
            for (int nh = 0; nh < 2; ++nh)
                ldsm4(bf[nh], smem_u32(bs + (b_row + nh * 16) * LDS + k0 + b_koff));
            #pragma unroll
            for (int mi = 0; mi < 4; ++mi)
                #pragma unroll
                for (int ni = 0; ni < 4; ++ni)
                    mma16816(acc[mi][ni], af[mi],
                             bf[ni >> 1][(ni & 1) * 2], bf[ni >> 1][(ni & 1) * 2 + 1]);
        }
        __syncthreads();
    }
}

// ---------------------------------------------------------------------------
// Kernel: QKV via HMMA.
// m<2 : C[i][o] = Xt[i,:]·W[o,:]  -> write T=Qt/Kt at [i][c] (+bias[o])
// m==2: C[o][j] = W[o,:]·Xt[j,:]  -> write Vb at [c][j] (+bias[o])
// grid (Nn/128, Cc/128, Bz*3), block 256
// ---------------------------------------------------------------------------
__global__ __launch_bounds__(256) void qkv_mma(
    const float* __restrict__ bq, const float* __restrict__ bk,
    const float* __restrict__ bv)
{
    int m = blockIdx.z % 3;
    int b = blockIdx.z / 3;
    const float* bias = (m == 0) ? bq : (m == 1) ? bk : bv;
    int n0 = blockIdx.x * 128;   // i or j
    int o0 = blockIdx.y * 128;   // channel o

    const __nv_bfloat16* Xt = g_Xt + (size_t)b * Nn * Cc + (size_t)n0 * Cc;
    const __nv_bfloat16* Wm = g_Wb + (size_t)m * Cc * Cc + (size_t)o0 * Cc;

    float acc[4][4][4] = {};
    if (m < 2) gemm_bf16<Cc, Cc, Cc / 32>(Xt, Wm, acc);
    else       gemm_bf16<Cc, Cc, Cc / 32>(Wm, Xt, acc);

    int lane = threadIdx.x & 31, wid = threadIdx.x >> 5;
    int wm = wid & 1, wn = wid >> 1;

    if (m < 2) {
        __nv_bfloat16* T = ((m == 0) ? g_Qt : g_Kt) + (size_t)b * Nn * Cc;
        #pragma unroll
        for (int mi = 0; mi < 4; ++mi) {
            int row = n0 + wm * 64 + mi * 16 + (lane >> 2);     // i
            #pragma unroll
            for (int ni = 0; ni < 4; ++ni) {
                int col = o0 + wn * 32 + ni * 8 + (lane & 3) * 2;  // c
                float b0v = bias[col], b1v = bias[col + 1];
                __nv_bfloat162 p0 = __floats2bfloat162_rn(acc[mi][ni][0] + b0v,
                                                          acc[mi][ni][1] + b1v);
                __nv_bfloat162 p1 = __floats2bfloat162_rn(acc[mi][ni][2] + b0v,
                                                          acc[mi][ni][3] + b1v);
                *(uint32_t*)&T[(size_t)row * Cc + col]       = *(uint32_t*)&p0;
                *(uint32_t*)&T[(size_t)(row + 8) * Cc + col] = *(uint32_t*)&p1;
            }
        }
    } else {
        __nv_bfloat16* Vb = g_Vb + (size_t)b * Cc * Nn;
        #pragma unroll
        for (int mi = 0; mi < 4; ++mi) {
            int row = o0 + wm * 64 + mi * 16 + (lane >> 2);     // c
            float b0v = bias[row], b1v = bias[row + 8];
            #pragma unroll
            for (int ni = 0; ni < 4; ++ni) {
                int col = n0 + wn * 32 + ni * 8 + (lane & 3) * 2;  // j
                __nv_bfloat162 p0 = __floats2bfloat162_rn(acc[mi][ni][0] + b0v,
                                                          acc[mi][ni][1] + b0v);
                __nv_bfloat162 p1 = __floats2bfloat162_rn(acc[mi][ni][2] + b1v,
                                                          acc[mi][ni][3] + b1v);
                *(uint32_t*)&Vb[(size_t)row * Nn + col]       = *(uint32_t*)&p0;
                *(uint32_t*)&Vb[(size_t)(row + 8) * Nn + col] = *(uint32_t*)&p1;
            }
        }
    }
}

// ---------------------------------------------------------------------------
// Fused flash attention: 512 threads (16 warps: 4m x 4n), grid (Nn/BM, Bz)
// ---------------------------------------------------------------------------
__device__ __forceinline__ void load_K(const __nv_bfloat16* Kg,
                                       __nv_bfloat16* Ks, int j0, int tid) {
    #pragma unroll
    for (int h = 0; h < 8; ++h) {
        int q = tid + h * 512;
        int r = q >> 5, cb = q & 31;
        CP_ASYNC16(smem_u32(Ks + r * SQK + cb * 8),
                   Kg + (size_t)(j0 + r) * Cc + cb * 8);
    }
    CP_COMMIT();
}
__device__ __forceinline__ void load_V(const __nv_bfloat16* Vg,
                                       __nv_bfloat16* Vs, int j0, int tid) {
    #pragma unroll
    for (int h = 0; h < 8; ++h) {
        int q = tid + h * 512;
        int r = q >> 4, cb = q & 15;
        CP_ASYNC16(smem_u32(Vs + r * SVP + cb * 8),
                   Vg + (size_t)r * Nn + j0 + cb * 8);
    }
    CP_COMMIT();
}

__global__ __launch_bounds__(512, 1) void flash_kernel(
    const float* __restrict__ x, float* __restrict__ out)
{
    extern __shared__ __nv_bfloat16 sm[];
    __shared__ float sm_mx[4 * 64], sm_sum[4 * 64];

    const int tid = threadIdx.x;
    const int lane = tid & 31, wid = tid >> 5;
    const int wm = wid & 3, wn = wid >> 2;
    const int b = blockIdx.y;
    const int i0 = blockIdx.x * BM;

    const __nv_bfloat16* Qg = g_Qt + (size_t)b * Nn * Cc + (size_t)i0 * Cc;
    const __nv_bfloat16* Kg = g_Kt + (size_t)b * Nn * Cc;
    const __nv_bfloat16* Vg = g_Vb + (size_t)b * Cc * Nn;

    __nv_bfloat16* Qs = sm + OFF_Q;
    __nv_bfloat16* Ks = sm + OFF_K;
    __nv_bfloat16* Vs = sm + OFF_V;
    __nv_bfloat16* Ps = sm + OFF_P;

    // prologue: {Q + K(0)} group 0, {V(0)} group 1
    #pragma unroll
    for (int h = 0; h < 4; ++h) {
        int q = tid + h * 512;
        int r = q >> 5, cb = q & 31;
        CP_ASYNC16(smem_u32(Qs + r * SQK + cb * 8), Qg + (size_t)r * Cc + cb * 8);
    }
    #pragma unroll
    for (int h = 0; h < 8; ++h) {
        int q = tid + h * 512;
        int r = q >> 5, cb = q & 31;
        CP_ASYNC16(smem_u32(Ks + r * SQK + cb * 8), Kg + (size_t)r * Cc + cb * 8);
    }
    CP_COMMIT();
    load_V(Vg, Vs, 0, tid);

    const int aA_row  = wm * 16 + (lane & 15);
    const int aA_koff = (lane >> 4) * 8;
    const int bK_row  = wn * 32 + (lane & 7) + ((lane >> 4) << 3);
    const int bV_row  = wn * 64 + (lane & 7) + ((lane >> 4) << 3);
    const int b_koff  = ((lane >> 3) & 1) * 8;
    const int r0l = wm * 16 + (lane >> 2);

    float dacc[8][4] = {};
    float m0 = -1e30f, m1 = -1e30f, l0 = 0.f, l1 = 0.f;

    #pragma unroll 1
    for (int t = 0; t < NSTEP; ++t) {
        CP_WAIT1();
        __syncthreads();

        // ---- S = (Q @ K^T) * scale (warp tile 16 x 32)
        float sacc[4][4] = {};
        #pragma unroll
        for (int ks = 0; ks < 16; ++ks) {
            uint32_t af[4];
            ldsm4(af, smem_u32(Qs + aA_row * SQK + ks * 16 + aA_koff));
            uint32_t bf[2][4];
            #pragma unroll
            for (int nh = 0; nh < 2; ++nh)
                ldsm4(bf[nh], smem_u32(Ks + (bK_row + nh * 16) * SQK + ks * 16 + b_koff));
            #pragma unroll
            for (int ni = 0; ni < 4; ++ni)
                mma16816(sacc[ni], af, bf[ni >> 1][(ni & 1) * 2],
                         bf[ni >> 1][(ni & 1) * 2 + 1]);
        }

        // ---- online softmax
        float tmx0 = -1e30f, tmx1 = -1e30f;
        #pragma unroll
        for (int ni = 0; ni < 4; ++ni) {
            sacc[ni][0] *= 0.0625f; sacc[ni][1] *= 0.0625f;
            sacc[ni][2] *= 0.0625f; sacc[ni][3] *= 0.0625f;
            tmx0 = fmaxf(tmx0, fmaxf(sacc[ni][0], sacc[ni][1]));
            tmx1 = fmaxf(tmx1, fmaxf(sacc[ni][2], sacc[ni][3]));
        }
        tmx0 = fmaxf(tmx0, __shfl_xor_sync(0xffffffffu, tmx0, 1));
        tmx0 = fmaxf(tmx0, __shfl_xor_sync(0xffffffffu, tmx0, 2));
        tmx1 = fmaxf(tmx1, __shfl_xor_sync(0xffffffffu, tmx1, 1));
        tmx1 = fmaxf(tmx1, __shfl_xor_sync(0xffffffffu, tmx1, 2));
        if ((lane & 3) == 0) {
            sm_mx[wn * 64 + r0l]     = tmx0;
            sm_mx[wn * 64 + r0l + 8] = tmx1;
        }
        __syncthreads();

        load_K(Kg, Ks, ((t + 1) & (NSTEP - 1)) * BN, tid);

        float mn0 = m0, mn1 = m1;
        #pragma unroll
        for (int g = 0; g < 4; ++g) {
            mn0 = fmaxf(mn0, sm_mx[g * 64 + r0l]);
            mn1 = fmaxf(mn1, sm_mx[g * 64 + r0l + 8]);
        }
        float al0 = __expf(m0 - mn0);
        float al1 = __expf(m1 - mn1);
        m0 = mn0; m1 = mn1;

        float ts0 = 0.f, ts1 = 0.f;
        uint32_t pp[4][2];
        #pragma unroll
        for (int ni = 0; ni < 4; ++ni) {
            float p0 = __expf(sacc[ni][0] - mn0);
            float p1 = __expf(sacc[ni][1] - mn0);
            float p2 = __expf(sacc[ni][2] - mn1);
            float p3 = __expf(sacc[ni][3] - mn1);
            ts0 += p0 + p1; ts1 += p2 + p3;
            __nv_bfloat162 q0 = __floats2bfloat162_rn(p0, p1);
            __nv_bfloat162 q1 = __floats2bfloat162_rn(p2, p3);
            pp[ni][0] = *(uint32_t*)&q0;
            pp[ni][1] = *(uint32_t*)&q1;
        }
        ts0 += __shfl_xor_sync(0xffffffffu, ts0, 1);
        ts0 += __shfl_xor_sync(0xffffffffu, ts0, 2);
        ts1 += __shfl_xor_sync(0xffffffffu, ts1, 1);
        ts1 += __shfl_xor_sync(0xffffffffu, ts1, 2);
        if ((lane & 3) == 0) {
            sm_sum[wn * 64 + r0l]     = ts0;
            sm_sum[wn * 64 + r0l + 8] = ts1;
        }
        __syncthreads();

        float ad0 = 0.f, ad1 = 0.f;
        #pragma unroll
        for (int g = 0; g < 4; ++g) {
            ad0 += sm_sum[g * 64 + r0l];
            ad1 += sm_sum[g * 64 + r0l + 8];
        }
        l0 = l0 * al0 + ad0;
        l1 = l1 * al1 + ad1;

        #pragma unroll
        for (int ni = 0; ni < 8; ++ni) {
            dacc[ni][0] *= al0; dacc[ni][1] *= al0;
            dacc[ni][2] *= al1; dacc[ni][3] *= al1;
        }

        // store P tile (bf16) to smem
        {
            int pc = wn * 32 + (lane & 3) * 2;
            #pragma unroll
            for (int ni = 0; ni < 4; ++ni) {
                *(uint32_t*)(Ps + r0l * SVP + pc + ni * 8)       = pp[ni][0];
                *(uint32_t*)(Ps + (r0l + 8) * SVP + pc + ni * 8) = pp[ni][1];
            }
        }

        CP_WAIT1();
        __syncthreads();

        // ---- D += P @ V^T (warp tile 16 x 64, k = 128)
        #pragma unroll
        for (int ks = 0; ks < 8; ++ks) {
            uint32_t af[4];
            ldsm4(af, smem_u32(Ps + aA_row * SVP + ks * 16 + aA_koff));
            uint32_t bf[4][4];
            #pragma unroll
            for (int nh = 0; nh < 4; ++nh)
                ldsm4(bf[nh], smem_u32(Vs + (bV_row + nh * 16) * SVP + ks * 16 + b_koff));
            #pragma unroll
            for (int ni = 0; ni < 8; ++ni)
                mma16816(dacc[ni], af, bf[ni >> 1][(ni & 1) * 2],
                         bf[ni >> 1][(ni & 1) * 2 + 1]);
        }
        __syncthreads();

        load_V(Vg, Vs, ((t + 1) & (NSTEP - 1)) * BN, tid);
    }

    // ---- epilogue: out = x + D / l
    float inv0 = 1.f / l0, inv1 = 1.f / l1;
    int gi = i0 + r0l;
    #pragma unroll
    for (int ni = 0; ni < 8; ++ni) {
        int c = wn * 64 + ni * 8 + (lane & 3) * 2;
        size_t b0a = ((size_t)b * Cc + c) * Nn;
        size_t b1a = b0a + Nn;
        out[b0a + gi]     = x[b0a + gi]     + dacc[ni][0] * inv0;
        out[b1a + gi]     = x[b1a + gi]     + dacc[ni][1] * inv0;
        out[b0a + gi + 8] = x[b0a + gi + 8] + dacc[ni][2] * inv1;
        out[b1a + gi + 8] = x[b1a + gi + 8] + dacc[ni][3] * inv1;
    }
}

// ---------------------------------------------------------------------------
extern "C" void kernel_launch(void* const* d_in, const int* in_sizes, int n_in,
                              void* d_out, int out_size)
{
    const float* x  = (const float*)d_in[0];
    const float* Wq = (const float*)d_in[1];
    const float* bq = (const float*)d_in[2];
    const float* Wk = (const float*)d_in[3];
    const float* bk = (const float*)d_in[4];
    const float* Wv = (const float*)d_in[5];
    const float* bv = (const float*)d_in[6];
    float* out = (float*)d_out;

    cudaFuncSetAttribute(flash_kernel,
                         cudaFuncAttributeMaxDynamicSharedMemorySize, SMEM_BYTES);

    wconv_kernel<<<dim3(64, 3), 256>>>(Wq, Wk, Wv);
    xpose_kernel<<<dim3(Nn / 32, Cc / 32, Bz), 256>>>(x);
    qkv_mma<<<dim3(Nn / 128, Cc / 128, Bz * 3), 256>>>(bq, bk, bv);
    flash_kernel<<<dim3(Nn / BM, Bz), 512, SMEM_BYTES>>>(x, out);
}

// round 8
// speedup vs baseline: 1.2238x; 1.2238x over previous
#include <cuda_runtime.h>
#include <cuda_bf16.h>
#include <cstdint>
#include <math.h>

#define Bz 4
#define Cc 256
#define Nn 4096
#define BM 64
#define BN 64
#define NSTEP (Nn / BN)   // 64

// ---------------- device scratch -------------------------------------------
__device__ __nv_bfloat16 g_Qt[(size_t)Bz * Nn * Cc];  // Q^T  [b][i][c]
__device__ __nv_bfloat16 g_Kt[(size_t)Bz * Nn * Cc];  // K^T  [b][j][c]
__device__ __nv_bfloat16 g_Vb[(size_t)Bz * Cc * Nn];  // V    [b][c][j]
__device__ __nv_bfloat16 g_Xt[(size_t)Bz * Nn * Cc];  // x^T  [b][n][c] bf16
__device__ __nv_bfloat16 g_Wb[3 * Cc * Cc];           // W bf16 [m][o][c]

// ---------------- PTX helpers (plain sm_103-safe) ---------------------------
__device__ __forceinline__ uint32_t smem_u32(const void* p) {
    uint32_t a;
    asm("{ .reg .u64 t; cvta.to.shared.u64 t, %1; cvt.u32.u64 %0, t; }"
        : "=r"(a) : "l"(p));
    return a;
}
__device__ __forceinline__ void ldsm4(uint32_t* r, uint32_t a) {
    asm volatile("ldmatrix.sync.aligned.m8n8.x4.shared.b16 {%0,%1,%2,%3}, [%4];"
                 : "=r"(r[0]), "=r"(r[1]), "=r"(r[2]), "=r"(r[3]) : "r"(a));
}
__device__ __forceinline__ void mma16816(float* c, const uint32_t* a,
                                         uint32_t b0, uint32_t b1) {
    asm volatile(
        "mma.sync.aligned.m16n8k16.row.col.f32.bf16.bf16.f32 "
        "{%0,%1,%2,%3}, {%4,%5,%6,%7}, {%8,%9}, {%0,%1,%2,%3};"
        : "+f"(c[0]), "+f"(c[1]), "+f"(c[2]), "+f"(c[3])
        : "r"(a[0]), "r"(a[1]), "r"(a[2]), "r"(a[3]), "r"(b0), "r"(b1));
}
#define CP_ASYNC16(dst, src) \
    asm volatile("cp.async.cg.shared.global [%0], [%1], 16;" :: "r"(dst), "l"(src))
#define CP_COMMIT() asm volatile("cp.async.commit_group;" ::: "memory")
#define CP_WAIT2()  asm volatile("cp.async.wait_group 2;" ::: "memory")
#define CP_WAIT1()  asm volatile("cp.async.wait_group 1;" ::: "memory")

// smem strides (bf16 elems)
#define SQK 264   // 528B rows: conflict-free ldmatrix
#define SV  72    // 144B rows: conflict-free ldmatrix
#define OFF_Q  0
#define OFF_K0 (64 * SQK)
#define OFF_K1 (OFF_K0 + 64 * SQK)
#define OFF_V  (OFF_K1 + 64 * SQK)
#define OFF_P  (OFF_V + 256 * SV)
#define SMEM_BYTES ((OFF_P + 64 * SV) * 2)   // 147456 B

// ---------------------------------------------------------------------------
// Prep A: W fp32 -> bf16. grid (64, 3), block 256
// ---------------------------------------------------------------------------
__global__ __launch_bounds__(256) void wconv_kernel(
    const float* __restrict__ Wq, const float* __restrict__ Wk,
    const float* __restrict__ Wv)
{
    int m = blockIdx.y;
    const float* W = (m == 0) ? Wq : (m == 1) ? Wk : Wv;
    int idx = (blockIdx.x * 256 + threadIdx.x) * 4;
    float4 v = *(const float4*)&W[idx];
    __nv_bfloat162 p[2];
    p[0] = __floats2bfloat162_rn(v.x, v.y);
    p[1] = __floats2bfloat162_rn(v.z, v.w);
    *(uint2*)&g_Wb[m * Cc * Cc + idx] = *(uint2*)p;
}

// ---------------------------------------------------------------------------
// Prep B: transpose-convert x [b][c][n] fp32 -> Xt [b][n][c] bf16
// ---------------------------------------------------------------------------
__global__ __launch_bounds__(256) void xpose_kernel(const float* __restrict__ x)
{
    __shared__ float tile[32][33];
    int b = blockIdx.z;
    int c0 = blockIdx.y * 32, n0 = blockIdx.x * 32;
    int tx = threadIdx.x & 31, ty = threadIdx.x >> 5;
    #pragma unroll
    for (int s = 0; s < 4; ++s)
        tile[ty + s * 8][tx] = x[((size_t)b * Cc + c0 + ty + s * 8) * Nn + n0 + tx];
    __syncthreads();
    #pragma unroll
    for (int s = 0; s < 4; ++s)
        g_Xt[((size_t)b * Nn + n0 + ty + s * 8) * Cc + c0 + tx] =
            __float2bfloat16(tile[tx][ty + s * 8]);
}

// ---------------------------------------------------------------------------
// Shared HMMA GEMM core: C[128x128] = A[128xK] B[128xK]^T (validated)
// ---------------------------------------------------------------------------
#define LDS 40

template<int LDGA, int LDGB, int KT>
__device__ __forceinline__ void gemm_bf16(
    const __nv_bfloat16* __restrict__ Ag,
    const __nv_bfloat16* __restrict__ Bg,
    float acc[4][4][4])
{
    __shared__ alignas(16) __nv_bfloat16 Asm[2][128 * LDS];
    __shared__ alignas(16) __nv_bfloat16 Bsm[2][128 * LDS];

    const int tid = threadIdx.x;
    const int lane = tid & 31, wid = tid >> 5;
    const int wm = wid & 1, wn = wid >> 1;
    const int r0 = tid >> 2, cb = tid & 3;

    auto load_tile = [&](int s, int kt) {
        int k0 = kt * 32;
        #pragma unroll
        for (int h = 0; h < 2; ++h) {
            int r = r0 + h * 64;
            CP_ASYNC16(smem_u32(&Asm[s][r * LDS + cb * 8]),
                       Ag + (size_t)r * LDGA + k0 + cb * 8);
            CP_ASYNC16(smem_u32(&Bsm[s][r * LDS + cb * 8]),
                       Bg + (size_t)r * LDGB + k0 + cb * 8);
        }
        CP_COMMIT();
    };

    const int a_row = wm * 64 + (lane & 15);
    const int a_koff = (lane >> 4) * 8;
    const int b_row = wn * 32 + (lane & 7) + ((lane >> 4) << 3);
    const int b_koff = ((lane >> 3) & 1) * 8;

    load_tile(0, 0);

    #pragma unroll 1
    for (int kt = 0; kt < KT; ++kt) {
        if (kt + 1 < KT) {
            load_tile((kt + 1) & 1, kt + 1);
            asm volatile("cp.async.wait_group 1;" ::: "memory");
        } else {
            asm volatile("cp.async.wait_group 0;" ::: "memory");
        }
        __syncthreads();

        const __nv_bfloat16* as = &Asm[kt & 1][0];
        const __nv_bfloat16* bs = &Bsm[kt & 1][0];

        #pragma unroll
        for (int ks = 0; ks < 2; ++ks) {
            int k0 = ks * 16;
            uint32_t af[4][4], bf[2][4];
            #pragma unroll
            for (int mi = 0; mi < 4; ++mi)
                ldsm4(af[mi], smem_u32(as + (a_row + mi * 16) * LDS + k0 + a_koff));
            #pragma unroll
            for (int nh = 0; nh < 2; ++nh)
                ldsm4(bf[nh], smem_u32(bs + (b_row + nh * 16) * LDS + k0 + b_koff));
            #pragma unroll
            for (int mi = 0; mi < 4; ++mi)
                #pragma unroll
                for (int ni = 0; ni < 4; ++ni)
                    mma16816(acc[mi][ni], af[mi],
                             bf[ni >> 1][(ni & 1) * 2], bf[ni >> 1][(ni & 1) * 2 + 1]);
        }
        __syncthreads();
    }
}

// ---------------------------------------------------------------------------
// QKV via HMMA (validated round 7)
// ---------------------------------------------------------------------------
__global__ __launch_bounds__(256) void qkv_mma(
    const float* __restrict__ bq, const float* __restrict__ bk,
    const float* __restrict__ bv)
{
    int m = blockIdx.z % 3;
    int b = blockIdx.z / 3;
    const float* bias = (m == 0) ? bq : (m == 1) ? bk : bv;
    int n0 = blockIdx.x * 128;
    int o0 = blockIdx.y * 128;

    const __nv_bfloat16* Xt = g_Xt + (size_t)b * Nn * Cc + (size_t)n0 * Cc;
    const __nv_bfloat16* Wm = g_Wb + (size_t)m * Cc * Cc + (size_t)o0 * Cc;

    float acc[4][4][4] = {};
    if (m < 2) gemm_bf16<Cc, Cc, Cc / 32>(Xt, Wm, acc);
    else       gemm_bf16<Cc, Cc, Cc / 32>(Wm, Xt, acc);

    int lane = threadIdx.x & 31, wid = threadIdx.x >> 5;
    int wm = wid & 1, wn = wid >> 1;

    if (m < 2) {
        __nv_bfloat16* T = ((m == 0) ? g_Qt : g_Kt) + (size_t)b * Nn * Cc;
        #pragma unroll
        for (int mi = 0; mi < 4; ++mi) {
            int row = n0 + wm * 64 + mi * 16 + (lane >> 2);
            #pragma unroll
            for (int ni = 0; ni < 4; ++ni) {
                int col = o0 + wn * 32 + ni * 8 + (lane & 3) * 2;
                float b0v = bias[col], b1v = bias[col + 1];
                __nv_bfloat162 p0 = __floats2bfloat162_rn(acc[mi][ni][0] + b0v,
                                                          acc[mi][ni][1] + b1v);
                __nv_bfloat162 p1 = __floats2bfloat162_rn(acc[mi][ni][2] + b0v,
                                                          acc[mi][ni][3] + b1v);
                *(uint32_t*)&T[(size_t)row * Cc + col]       = *(uint32_t*)&p0;
                *(uint32_t*)&T[(size_t)(row + 8) * Cc + col] = *(uint32_t*)&p1;
            }
        }
    } else {
        __nv_bfloat16* Vb = g_Vb + (size_t)b * Cc * Nn;
        #pragma unroll
        for (int mi = 0; mi < 4; ++mi) {
            int row = o0 + wm * 64 + mi * 16 + (lane >> 2);
            float b0v = bias[row], b1v = bias[row + 8];
            #pragma unroll
            for (int ni = 0; ni < 4; ++ni) {
                int col = n0 + wn * 32 + ni * 8 + (lane & 3) * 2;
                __nv_bfloat162 p0 = __floats2bfloat162_rn(acc[mi][ni][0] + b0v,
                                                          acc[mi][ni][1] + b0v);
                __nv_bfloat162 p1 = __floats2bfloat162_rn(acc[mi][ni][2] + b1v,
                                                          acc[mi][ni][3] + b1v);
                *(uint32_t*)&Vb[(size_t)row * Nn + col]       = *(uint32_t*)&p0;
                *(uint32_t*)&Vb[(size_t)(row + 8) * Nn + col] = *(uint32_t*)&p1;
            }
        }
    }
}

// ---------------------------------------------------------------------------
// Fused flash attention, software-pipelined. 256 threads (8 warps: 4m x 2n).
// ---------------------------------------------------------------------------
__device__ __forceinline__ void load_K(const __nv_bfloat16* Kg,
                                       __nv_bfloat16* Ks, int j0, int tid) {
    #pragma unroll
    for (int h = 0; h < 8; ++h) {
        int q = tid + h * 256;
        int r = q >> 5, cb = q & 31;
        CP_ASYNC16(smem_u32(Ks + r * SQK + cb * 8),
                   Kg + (size_t)(j0 + r) * Cc + cb * 8);
    }
    CP_COMMIT();
}
__device__ __forceinline__ void load_V(const __nv_bfloat16* Vg,
                                       __nv_bfloat16* Vs, int j0, int tid) {
    #pragma unroll
    for (int h = 0; h < 8; ++h) {
        int q = tid + h * 256;
        int r = q >> 3, cb = q & 7;
        CP_ASYNC16(smem_u32(Vs + r * SV + cb * 8),
                   Vg + (size_t)r * Nn + j0 + cb * 8);
    }
    CP_COMMIT();
}

__global__ __launch_bounds__(256, 1) void flash_kernel(
    const float* __restrict__ x, float* __restrict__ out)
{
    extern __shared__ __nv_bfloat16 sm[];
    __shared__ float sm_mx[128], sm_sum[128];

    const int tid = threadIdx.x;
    const int lane = tid & 31, wid = tid >> 5;
    const int wm = wid & 3, wn = wid >> 2;
    const int b = blockIdx.y;
    const int i0 = blockIdx.x * BM;

    const __nv_bfloat16* Qg = g_Qt + (size_t)b * Nn * Cc + (size_t)i0 * Cc;
    const __nv_bfloat16* Kg = g_Kt + (size_t)b * Nn * Cc;
    const __nv_bfloat16* Vg = g_Vb + (size_t)b * Cc * Nn;

    __nv_bfloat16* Qs = sm + OFF_Q;
    __nv_bfloat16* KsA = sm + OFF_K0;
    __nv_bfloat16* KsB = sm + OFF_K1;
    __nv_bfloat16* Vs = sm + OFF_V;
    __nv_bfloat16* Ps = sm + OFF_P;

    // prologue: g0 = {Q, K(0)}, g1 = {K(1)}, g2 = {V(0)}
    #pragma unroll
    for (int h = 0; h < 8; ++h) {
        int q = tid + h * 256;
        int r = q >> 5, cb = q & 31;
        CP_ASYNC16(smem_u32(Qs + r * SQK + cb * 8), Qg + (size_t)r * Cc + cb * 8);
        CP_ASYNC16(smem_u32(KsA + r * SQK + cb * 8), Kg + (size_t)r * Cc + cb * 8);
    }
    CP_COMMIT();
    load_K(Kg, KsB, BN, tid);
    load_V(Vg, Vs, 0, tid);

    const int aA_row  = wm * 16 + (lane & 15);
    const int aA_koff = (lane >> 4) * 8;
    const int bK_row  = wn * 32 + (lane & 7) + ((lane >> 4) << 3);
    const int bV_row  = wn * 128 + (lane & 7) + ((lane >> 4) << 3);
    const int b_koff  = ((lane >> 3) & 1) * 8;
    const int r0l = wm * 16 + (lane >> 2);

    // S MMA block: warp tile 16 x 32, k = 256
    auto s_mma = [&](const __nv_bfloat16* Kbase, float sx[4][4]) {
        #pragma unroll
        for (int ks = 0; ks < 16; ++ks) {
            uint32_t af[4];
            ldsm4(af, smem_u32(Qs + aA_row * SQK + ks * 16 + aA_koff));
            uint32_t bf[2][4];
            #pragma unroll
            for (int nh = 0; nh < 2; ++nh)
                ldsm4(bf[nh], smem_u32(Kbase + (bK_row + nh * 16) * SQK + ks * 16 + b_koff));
            #pragma unroll
            for (int ni = 0; ni < 4; ++ni)
                mma16816(sx[ni], af, bf[ni >> 1][(ni & 1) * 2],
                         bf[ni >> 1][(ni & 1) * 2 + 1]);
        }
    };

    float dacc[16][4] = {};
    float scur[4][4] = {};
    float m0 = -1e30f, m1 = -1e30f, l0 = 0.f, l1 = 0.f;

    // fill: S(0)
    CP_WAIT2();          // g0 (Q, K0) done
    __syncthreads();
    s_mma(KsA, scur);

    #pragma unroll 1
    for (int t = 0; t < NSTEP; ++t) {
        __nv_bfloat16* KsCur  = (t & 1) ? KsB : KsA;       // holds K(t) (free now)
        __nv_bfloat16* KsNext = (t & 1) ? KsA : KsB;       // holds K(t+1)

        // issue K(t+2) into the freed buffer
        load_K(Kg, KsCur, ((t + 2) & (NSTEP - 1)) * BN, tid);

        CP_WAIT2();            // K(t+1) resident (V(t), K(t+2) may pend)
        __syncthreads();

        // ---- S(t+1) MMAs issued now; tensor pipe drains under softmax(t)
        float snx[4][4] = {};
        if (t + 1 < NSTEP) s_mma(KsNext, snx);

        // ---- online softmax on scur
        float tmx0 = -1e30f, tmx1 = -1e30f;
        #pragma unroll
        for (int ni = 0; ni < 4; ++ni) {
            scur[ni][0] *= 0.0625f; scur[ni][1] *= 0.0625f;
            scur[ni][2] *= 0.0625f; scur[ni][3] *= 0.0625f;
            tmx0 = fmaxf(tmx0, fmaxf(scur[ni][0], scur[ni][1]));
            tmx1 = fmaxf(tmx1, fmaxf(scur[ni][2], scur[ni][3]));
        }
        tmx0 = fmaxf(tmx0, __shfl_xor_sync(0xffffffffu, tmx0, 1));
        tmx0 = fmaxf(tmx0, __shfl_xor_sync(0xffffffffu, tmx0, 2));
        tmx1 = fmaxf(tmx1, __shfl_xor_sync(0xffffffffu, tmx1, 1));
        tmx1 = fmaxf(tmx1, __shfl_xor_sync(0xffffffffu, tmx1, 2));
        if ((lane & 3) == 0) {
            sm_mx[wn * 64 + r0l]     = tmx0;
            sm_mx[wn * 64 + r0l + 8] = tmx1;
        }
        __syncthreads();

        float mn0 = fmaxf(m0, fmaxf(sm_mx[r0l],     sm_mx[64 + r0l]));
        float mn1 = fmaxf(m1, fmaxf(sm_mx[r0l + 8], sm_mx[64 + r0l + 8]));
        float al0 = __expf(m0 - mn0);
        float al1 = __expf(m1 - mn1);
        m0 = mn0; m1 = mn1;

        float ts0 = 0.f, ts1 = 0.f;
        uint32_t pp[4][2];
        #pragma unroll
        for (int ni = 0; ni < 4; ++ni) {
            float p0 = __expf(scur[ni][0] - mn0);
            float p1 = __expf(scur[ni][1] - mn0);
            float p2 = __expf(scur[ni][2] - mn1);
            float p3 = __expf(scur[ni][3] - mn1);
            ts0 += p0 + p1; ts1 += p2 + p3;
            __nv_bfloat162 q0 = __floats2bfloat162_rn(p0, p1);
            __nv_bfloat162 q1 = __floats2bfloat162_rn(p2, p3);
            pp[ni][0] = *(uint32_t*)&q0;
            pp[ni][1] = *(uint32_t*)&q1;
        }
        ts0 += __shfl_xor_sync(0xffffffffu, ts0, 1);
        ts0 += __shfl_xor_sync(0xffffffffu, ts0, 2);
        ts1 += __shfl_xor_sync(0xffffffffu, ts1, 1);
        ts1 += __shfl_xor_sync(0xffffffffu, ts1, 2);
        if ((lane & 3) == 0) {
            sm_sum[wn * 64 + r0l]     = ts0;
            sm_sum[wn * 64 + r0l + 8] = ts1;
        }
        __syncthreads();

        l0 = l0 * al0 + sm_sum[r0l]     + sm_sum[64 + r0l];
        l1 = l1 * al1 + sm_sum[r0l + 8] + sm_sum[64 + r0l + 8];

        #pragma unroll
        for (int ni = 0; ni < 16; ++ni) {
            dacc[ni][0] *= al0; dacc[ni][1] *= al0;
            dacc[ni][2] *= al1; dacc[ni][3] *= al1;
        }

        // store P(t) tile (bf16)
        {
            int pc = wn * 32 + (lane & 3) * 2;
            #pragma unroll
            for (int ni = 0; ni < 4; ++ni) {
                *(uint32_t*)(Ps + r0l * SV + pc + ni * 8)       = pp[ni][0];
                *(uint32_t*)(Ps + (r0l + 8) * SV + pc + ni * 8) = pp[ni][1];
            }
        }

        CP_WAIT1();            // V(t) resident (K(t+2) may pend)
        __syncthreads();       // P + V visible to all

        // ---- D += P(t) @ V(t)^T (warp tile 16 x 128, k = 64)
        #pragma unroll
        for (int ks = 0; ks < 4; ++ks) {
            uint32_t af[4];
            ldsm4(af, smem_u32(Ps + aA_row * SV + ks * 16 + aA_koff));
            uint32_t bf[8][4];
            #pragma unroll
            for (int nh = 0; nh < 8; ++nh)
                ldsm4(bf[nh], smem_u32(Vs + (bV_row + nh * 16) * SV + ks * 16 + b_koff));
            #pragma unroll
            for (int ni = 0; ni < 16; ++ni)
                mma16816(dacc[ni], af, bf[ni >> 1][(ni & 1) * 2],
                         bf[ni >> 1][(ni & 1) * 2 + 1]);
        }
        __syncthreads();       // V, P consumed

        load_V(Vg, Vs, ((t + 1) & (NSTEP - 1)) * BN, tid);   // V(t+1)

        // rotate S accumulators
        if (t + 1 < NSTEP) {
            #pragma unroll
            for (int ni = 0; ni < 4; ++ni) {
                scur[ni][0] = snx[ni][0]; scur[ni][1] = snx[ni][1];
                scur[ni][2] = snx[ni][2]; scur[ni][3] = snx[ni][3];
            }
        }
    }

    // ---- epilogue: out = x + D / l
    float inv0 = 1.f / l0, inv1 = 1.f / l1;
    int gi = i0 + r0l;
    #pragma unroll
    for (int ni = 0; ni < 16; ++ni) {
        int c = wn * 128 + ni * 8 + (lane & 3) * 2;
        size_t b0a = ((size_t)b * Cc + c) * Nn;
        size_t b1a = b0a + Nn;
        out[b0a + gi]     = x[b0a + gi]     + dacc[ni][0] * inv0;
        out[b1a + gi]     = x[b1a + gi]     + dacc[ni][1] * inv0;
        out[b0a + gi + 8] = x[b0a + gi + 8] + dacc[ni][2] * inv1;
        out[b1a + gi + 8] = x[b1a + gi + 8] + dacc[ni][3] * inv1;
    }
}

// ---------------------------------------------------------------------------
extern "C" void kernel_launch(void* const* d_in, const int* in_sizes, int n_in,
                              void* d_out, int out_size)
{
    const float* x  = (const float*)d_in[0];
    const float* Wq = (const float*)d_in[1];
    const float* bq = (const float*)d_in[2];
    const float* Wk = (const float*)d_in[3];
    const float* bk = (const float*)d_in[4];
    const float* Wv = (const float*)d_in[5];
    const float* bv = (const float*)d_in[6];
    float* out = (float*)d_out;

    cudaFuncSetAttribute(flash_kernel,
                         cudaFuncAttributeMaxDynamicSharedMemorySize, SMEM_BYTES);

    wconv_kernel<<<dim3(64, 3), 256>>>(Wq, Wk, Wv);
    xpose_kernel<<<dim3(Nn / 32, Cc / 32, Bz), 256>>>(x);
    qkv_mma<<<dim3(Nn / 128, Cc / 128, Bz * 3), 256>>>(bq, bk, bv);
    flash_kernel<<<dim3(Nn / BM, Bz), 256, SMEM_BYTES>>>(x, out);
}

// round 9
// speedup vs baseline: 1.3428x; 1.0973x over previous
#include <cuda_runtime.h>
#include <cuda_bf16.h>
#include <cstdint>
#include <math.h>

#define Bz 4
#define Cc 256
#define Nn 4096
#define BM 64
#define BN 64
#define NSTEP (Nn / BN)   // 64

// ---------------- device scratch -------------------------------------------
__device__ __nv_bfloat16 g_Qt[(size_t)Bz * Nn * Cc];  // Q^T  [b][i][c]
__device__ __nv_bfloat16 g_Kt[(size_t)Bz * Nn * Cc];  // K^T  [b][j][c]
__device__ __nv_bfloat16 g_Vb[(size_t)Bz * Cc * Nn];  // V    [b][c][j]
__device__ __nv_bfloat16 g_Xt[(size_t)Bz * Nn * Cc];  // x^T  [b][n][c] bf16
__device__ __nv_bfloat16 g_Wb[3 * Cc * Cc];           // W bf16 [m][o][c]

// ---------------- PTX helpers (plain sm_103-safe) ---------------------------
__device__ __forceinline__ uint32_t smem_u32(const void* p) {
    uint32_t a;
    asm("{ .reg .u64 t; cvta.to.shared.u64 t, %1; cvt.u32.u64 %0, t; }"
        : "=r"(a) : "l"(p));
    return a;
}
__device__ __forceinline__ void ldsm4(uint32_t* r, uint32_t a) {
    asm volatile("ldmatrix.sync.aligned.m8n8.x4.shared.b16 {%0,%1,%2,%3}, [%4];"
                 : "=r"(r[0]), "=r"(r[1]), "=r"(r[2]), "=r"(r[3]) : "r"(a));
}
__device__ __forceinline__ void mma16816(float* c, const uint32_t* a,
                                         uint32_t b0, uint32_t b1) {
    asm volatile(
        "mma.sync.aligned.m16n8k16.row.col.f32.bf16.bf16.f32 "
        "{%0,%1,%2,%3}, {%4,%5,%6,%7}, {%8,%9}, {%0,%1,%2,%3};"
        : "+f"(c[0]), "+f"(c[1]), "+f"(c[2]), "+f"(c[3])
        : "r"(a[0]), "r"(a[1]), "r"(a[2]), "r"(a[3]), "r"(b0), "r"(b1));
}
#define CP_ASYNC16(dst, src) \
    asm volatile("cp.async.cg.shared.global [%0], [%1], 16;" :: "r"(dst), "l"(src))
#define CP_COMMIT() asm volatile("cp.async.commit_group;" ::: "memory")
#define CP_WAIT2()  asm volatile("cp.async.wait_group 2;" ::: "memory")
#define CP_WAIT1()  asm volatile("cp.async.wait_group 1;" ::: "memory")

// smem strides (bf16 elems); 528B / 144B rows -> conflict-free ldmatrix
#define SQK 264
#define SV  72
#define OFF_Q  0
#define OFF_K0 (64 * SQK)
#define OFF_K1 (OFF_K0 + 64 * SQK)
#define OFF_V  (OFF_K1 + 64 * SQK)
#define OFF_P  (OFF_V + 256 * SV)
#define SMEM_BYTES ((OFF_P + 64 * SV) * 2)   // 147456 B

// ---------------------------------------------------------------------------
// Prep A: W fp32 -> bf16. grid (64, 3), block 256
// ---------------------------------------------------------------------------
__global__ __launch_bounds__(256) void wconv_kernel(
    const float* __restrict__ Wq, const float* __restrict__ Wk,
    const float* __restrict__ Wv)
{
    int m = blockIdx.y;
    const float* W = (m == 0) ? Wq : (m == 1) ? Wk : Wv;
    int idx = (blockIdx.x * 256 + threadIdx.x) * 4;
    float4 v = *(const float4*)&W[idx];
    __nv_bfloat162 p[2];
    p[0] = __floats2bfloat162_rn(v.x, v.y);
    p[1] = __floats2bfloat162_rn(v.z, v.w);
    *(uint2*)&g_Wb[m * Cc * Cc + idx] = *(uint2*)p;
}

// ---------------------------------------------------------------------------
// Prep B: transpose-convert x [b][c][n] fp32 -> Xt [b][n][c] bf16
// ---------------------------------------------------------------------------
__global__ __launch_bounds__(256) void xpose_kernel(const float* __restrict__ x)
{
    __shared__ float tile[32][33];
    int b = blockIdx.z;
    int c0 = blockIdx.y * 32, n0 = blockIdx.x * 32;
    int tx = threadIdx.x & 31, ty = threadIdx.x >> 5;
    #pragma unroll
    for (int s = 0; s < 4; ++s)
        tile[ty + s * 8][tx] = x[((size_t)b * Cc + c0 + ty + s * 8) * Nn + n0 + tx];
    __syncthreads();
    #pragma unroll
    for (int s = 0; s < 4; ++s)
        g_Xt[((size_t)b * Nn + n0 + ty + s * 8) * Cc + c0 + tx] =
            __float2bfloat16(tile[tx][ty + s * 8]);
}

// ---------------------------------------------------------------------------
// Shared HMMA GEMM core (validated): C[128x128] = A[128xK] B[128xK]^T
// ---------------------------------------------------------------------------
#define LDS 40

template<int LDGA, int LDGB, int KT>
__device__ __forceinline__ void gemm_bf16(
    const __nv_bfloat16* __restrict__ Ag,
    const __nv_bfloat16* __restrict__ Bg,
    float acc[4][4][4])
{
    __shared__ alignas(16) __nv_bfloat16 Asm[2][128 * LDS];
    __shared__ alignas(16) __nv_bfloat16 Bsm[2][128 * LDS];

    const int tid = threadIdx.x;
    const int lane = tid & 31, wid = tid >> 5;
    const int wm = wid & 1, wn = wid >> 1;
    const int r0 = tid >> 2, cb = tid & 3;

    auto load_tile = [&](int s, int kt) {
        int k0 = kt * 32;
        #pragma unroll
        for (int h = 0; h < 2; ++h) {
            int r = r0 + h * 64;
            CP_ASYNC16(smem_u32(&Asm[s][r * LDS + cb * 8]),
                       Ag + (size_t)r * LDGA + k0 + cb * 8);
            CP_ASYNC16(smem_u32(&Bsm[s][r * LDS + cb * 8]),
                       Bg + (size_t)r * LDGB + k0 + cb * 8);
        }
        CP_COMMIT();
    };

    const int a_row = wm * 64 + (lane & 15);
    const int a_koff = (lane >> 4) * 8;
    const int b_row = wn * 32 + (lane & 7) + ((lane >> 4) << 3);
    const int b_koff = ((lane >> 3) & 1) * 8;

    load_tile(0, 0);

    #pragma unroll 1
    for (int kt = 0; kt < KT; ++kt) {
        if (kt + 1 < KT) {
            load_tile((kt + 1) & 1, kt + 1);
            asm volatile("cp.async.wait_group 1;" ::: "memory");
        } else {
            asm volatile("cp.async.wait_group 0;" ::: "memory");
        }
        __syncthreads();

        const __nv_bfloat16* as = &Asm[kt & 1][0];
        const __nv_bfloat16* bs = &Bsm[kt & 1][0];

        #pragma unroll
        for (int ks = 0; ks < 2; ++ks) {
            int k0 = ks * 16;
            uint32_t af[4][4], bf[2][4];
            #pragma unroll
            for (int mi = 0; mi < 4; ++mi)
                ldsm4(af[mi], smem_u32(as + (a_row + mi * 16) * LDS + k0 + a_koff));
            #pragma unroll
            for (int nh = 0; nh < 2; ++nh)
                ldsm4(bf[nh], smem_u32(bs + (b_row + nh * 16) * LDS + k0 + b_koff));
            #pragma unroll
            for (int mi = 0; mi < 4; ++mi)
                #pragma unroll
                for (int ni = 0; ni < 4; ++ni)
                    mma16816(acc[mi][ni], af[mi],
                             bf[ni >> 1][(ni & 1) * 2], bf[ni >> 1][(ni & 1) * 2 + 1]);
        }
        __syncthreads();
    }
}

// ---------------------------------------------------------------------------
// QKV via HMMA (validated)
// ---------------------------------------------------------------------------
__global__ __launch_bounds__(256) void qkv_mma(
    const float* __restrict__ bq, const float* __restrict__ bk,
    const float* __restrict__ bv)
{
    int m = blockIdx.z % 3;
    int b = blockIdx.z / 3;
    const float* bias = (m == 0) ? bq : (m == 1) ? bk : bv;
    int n0 = blockIdx.x * 128;
    int o0 = blockIdx.y * 128;

    const __nv_bfloat16* Xt = g_Xt + (size_t)b * Nn * Cc + (size_t)n0 * Cc;
    const __nv_bfloat16* Wm = g_Wb + (size_t)m * Cc * Cc + (size_t)o0 * Cc;

    float acc[4][4][4] = {};
    if (m < 2) gemm_bf16<Cc, Cc, Cc / 32>(Xt, Wm, acc);
    else       gemm_bf16<Cc, Cc, Cc / 32>(Wm, Xt, acc);

    int lane = threadIdx.x & 31, wid = threadIdx.x >> 5;
    int wm = wid & 1, wn = wid >> 1;

    if (m < 2) {
        __nv_bfloat16* T = ((m == 0) ? g_Qt : g_Kt) + (size_t)b * Nn * Cc;
        #pragma unroll
        for (int mi = 0; mi < 4; ++mi) {
            int row = n0 + wm * 64 + mi * 16 + (lane >> 2);
            #pragma unroll
            for (int ni = 0; ni < 4; ++ni) {
                int col = o0 + wn * 32 + ni * 8 + (lane & 3) * 2;
                float b0v = bias[col], b1v = bias[col + 1];
                __nv_bfloat162 p0 = __floats2bfloat162_rn(acc[mi][ni][0] + b0v,
                                                          acc[mi][ni][1] + b1v);
                __nv_bfloat162 p1 = __floats2bfloat162_rn(acc[mi][ni][2] + b0v,
                                                          acc[mi][ni][3] + b1v);
                *(uint32_t*)&T[(size_t)row * Cc + col]       = *(uint32_t*)&p0;
                *(uint32_t*)&T[(size_t)(row + 8) * Cc + col] = *(uint32_t*)&p1;
            }
        }
    } else {
        __nv_bfloat16* Vb = g_Vb + (size_t)b * Cc * Nn;
        #pragma unroll
        for (int mi = 0; mi < 4; ++mi) {
            int row = o0 + wm * 64 + mi * 16 + (lane >> 2);
            float b0v = bias[row], b1v = bias[row + 8];
            #pragma unroll
            for (int ni = 0; ni < 4; ++ni) {
                int col = n0 + wn * 32 + ni * 8 + (lane & 3) * 2;
                __nv_bfloat162 p0 = __floats2bfloat162_rn(acc[mi][ni][0] + b0v,
                                                          acc[mi][ni][1] + b0v);
                __nv_bfloat162 p1 = __floats2bfloat162_rn(acc[mi][ni][2] + b1v,
                                                          acc[mi][ni][3] + b1v);
                *(uint32_t*)&Vb[(size_t)row * Nn + col]       = *(uint32_t*)&p0;
                *(uint32_t*)&Vb[(size_t)(row + 8) * Nn + col] = *(uint32_t*)&p1;
            }
        }
    }
}

// ---------------------------------------------------------------------------
// Fused flash attention. 256 threads, 8 warps.
// S phase: 4m x 2n, Q cached in registers. PV phase: 2m' x 4n' (V dup x2).
// Row stats (m, l, alpha) in smem; 3 syncs/step.
// ---------------------------------------------------------------------------
__device__ __forceinline__ void load_K(const __nv_bfloat16* Kg,
                                       __nv_bfloat16* Ks, int j0, int tid) {
    #pragma unroll
    for (int h = 0; h < 8; ++h) {
        int q = tid + h * 256;
        int r = q >> 5, cb = q & 31;
        CP_ASYNC16(smem_u32(Ks + r * SQK + cb * 8),
                   Kg + (size_t)(j0 + r) * Cc + cb * 8);
    }
    CP_COMMIT();
}
__device__ __forceinline__ void load_V(const __nv_bfloat16* Vg,
                                       __nv_bfloat16* Vs, int j0, int tid) {
    #pragma unroll
    for (int h = 0; h < 8; ++h) {
        int q = tid + h * 256;
        int r = q >> 3, cb = q & 7;
        CP_ASYNC16(smem_u32(Vs + r * SV + cb * 8),
                   Vg + (size_t)r * Nn + j0 + cb * 8);
    }
    CP_COMMIT();
}

__global__ __launch_bounds__(256, 1) void flash_kernel(
    const float* __restrict__ x, float* __restrict__ out)
{
    extern __shared__ __nv_bfloat16 sm[];
    __shared__ float s_mx[2][64], s_sum[2][64];
    __shared__ float s_m[2][64], s_l[2][64], s_alpha[64];

    const int tid = threadIdx.x;
    const int lane = tid & 31, wid = tid >> 5;
    const int wm = wid & 3, wn = wid >> 2;      // S layout: 4m x 2n
    const int pm = wid & 1, pn = wid >> 1;      // PV layout: 2m' x 4n'
    const int b = blockIdx.y;
    const int i0 = blockIdx.x * BM;

    const __nv_bfloat16* Qg = g_Qt + (size_t)b * Nn * Cc + (size_t)i0 * Cc;
    const __nv_bfloat16* Kg = g_Kt + (size_t)b * Nn * Cc;
    const __nv_bfloat16* Vg = g_Vb + (size_t)b * Cc * Nn;

    __nv_bfloat16* Qs  = sm + OFF_Q;
    __nv_bfloat16* KsA = sm + OFF_K0;
    __nv_bfloat16* KsB = sm + OFF_K1;
    __nv_bfloat16* Vs  = sm + OFF_V;
    __nv_bfloat16* Ps  = sm + OFF_P;

    if (tid < 64) { s_m[0][tid] = -1e30f; s_l[0][tid] = 0.f; }

    // prologue: G1={Q,K0}, G2={K1}, G3={V0}
    #pragma unroll
    for (int h = 0; h < 8; ++h) {
        int q = tid + h * 256;
        int r = q >> 5, cb = q & 31;
        CP_ASYNC16(smem_u32(Qs + r * SQK + cb * 8), Qg + (size_t)r * Cc + cb * 8);
        CP_ASYNC16(smem_u32(KsA + r * SQK + cb * 8), Kg + (size_t)r * Cc + cb * 8);
    }
    CP_COMMIT();
    load_K(Kg, KsB, BN, tid);
    load_V(Vg, Vs, 0, tid);

    const int aA_row  = wm * 16 + (lane & 15);
    const int aA_koff = (lane >> 4) * 8;
    const int bK_row  = wn * 32 + (lane & 7) + ((lane >> 4) << 3);
    const int b_koff  = ((lane >> 3) & 1) * 8;
    const int r0l = wm * 16 + (lane >> 2);          // S stats rows
    const int aP_row  = pm * 32 + (lane & 15);       // PV A (P) rows
    const int bV_row  = pn * 64 + (lane & 7) + ((lane >> 4) << 3);
    const int pr0 = pm * 32 + (lane >> 2);           // PV dacc rows

    CP_WAIT2();             // Q + K0 resident
    __syncthreads();

    // cache Q fragments in registers (constant across all steps)
    uint32_t qf[16][4];
    #pragma unroll
    for (int ks = 0; ks < 16; ++ks)
        ldsm4(qf[ks], smem_u32(Qs + aA_row * SQK + ks * 16 + aA_koff));

    float dacc[2][8][4] = {};

    #pragma unroll 1
    for (int t = 0; t < NSTEP; ++t) {
        __nv_bfloat16* Kcur = (t & 1) ? KsB : KsA;

        // ---- S(t) = Q @ K(t)^T : warp tile 16 x 32, A from registers
        float sacc[4][4] = {};
        #pragma unroll
        for (int ks = 0; ks < 16; ++ks) {
            uint32_t bf[2][4];
            #pragma unroll
            for (int nh = 0; nh < 2; ++nh)
                ldsm4(bf[nh], smem_u32(Kcur + (bK_row + nh * 16) * SQK + ks * 16 + b_koff));
            #pragma unroll
            for (int ni = 0; ni < 4; ++ni)
                mma16816(sacc[ni], qf[ks], bf[ni >> 1][(ni & 1) * 2],
                         bf[ni >> 1][(ni & 1) * 2 + 1]);
        }

        // ---- row max partials
        float tmx0 = -1e30f, tmx1 = -1e30f;
        #pragma unroll
        for (int ni = 0; ni < 4; ++ni) {
            sacc[ni][0] *= 0.0625f; sacc[ni][1] *= 0.0625f;
            sacc[ni][2] *= 0.0625f; sacc[ni][3] *= 0.0625f;
            tmx0 = fmaxf(tmx0, fmaxf(sacc[ni][0], sacc[ni][1]));
            tmx1 = fmaxf(tmx1, fmaxf(sacc[ni][2], sacc[ni][3]));
        }
        tmx0 = fmaxf(tmx0, __shfl_xor_sync(0xffffffffu, tmx0, 1));
        tmx0 = fmaxf(tmx0, __shfl_xor_sync(0xffffffffu, tmx0, 2));
        tmx1 = fmaxf(tmx1, __shfl_xor_sync(0xffffffffu, tmx1, 1));
        tmx1 = fmaxf(tmx1, __shfl_xor_sync(0xffffffffu, tmx1, 2));
        if ((lane & 3) == 0) {
            s_mx[wn][r0l]     = tmx0;
            s_mx[wn][r0l + 8] = tmx1;
        }
        __syncthreads();                                   // sync #1

        // K(t) buffer free -> issue K(t+2) into it
        load_K(Kg, Kcur, ((t + 2) & (NSTEP - 1)) * BN, tid);

        // ---- softmax B: global max, alpha, exp, pack, partial sums
        const int rp = t & 1, rq = rp ^ 1;
        float mo0 = s_m[rp][r0l], mo1 = s_m[rp][r0l + 8];
        float mn0 = fmaxf(mo0, fmaxf(s_mx[0][r0l],     s_mx[1][r0l]));
        float mn1 = fmaxf(mo1, fmaxf(s_mx[0][r0l + 8], s_mx[1][r0l + 8]));
        float al0 = __expf(mo0 - mn0);
        float al1 = __expf(mo1 - mn1);
        if (wn == 0 && (lane & 3) == 0) {
            s_m[rq][r0l] = mn0;  s_m[rq][r0l + 8] = mn1;
            s_alpha[r0l] = al0;  s_alpha[r0l + 8] = al1;
        }

        float ts0 = 0.f, ts1 = 0.f;
        uint32_t pp[4][2];
        #pragma unroll
        for (int ni = 0; ni < 4; ++ni) {
            float p0 = __expf(sacc[ni][0] - mn0);
            float p1 = __expf(sacc[ni][1] - mn0);
            float p2 = __expf(sacc[ni][2] - mn1);
            float p3 = __expf(sacc[ni][3] - mn1);
            ts0 += p0 + p1; ts1 += p2 + p3;
            __nv_bfloat162 q0 = __floats2bfloat162_rn(p0, p1);
            __nv_bfloat162 q1 = __floats2bfloat162_rn(p2, p3);
            pp[ni][0] = *(uint32_t*)&q0;
            pp[ni][1] = *(uint32_t*)&q1;
        }
        ts0 += __shfl_xor_sync(0xffffffffu, ts0, 1);
        ts0 += __shfl_xor_sync(0xffffffffu, ts0, 2);
        ts1 += __shfl_xor_sync(0xffffffffu, ts1, 1);
        ts1 += __shfl_xor_sync(0xffffffffu, ts1, 2);
        if ((lane & 3) == 0) {
            s_sum[wn][r0l]     = ts0;
            s_sum[wn][r0l + 8] = ts1;
        }

        // store P(t) tile
        {
            int pc = wn * 32 + (lane & 3) * 2;
            #pragma unroll
            for (int ni = 0; ni < 4; ++ni) {
                *(uint32_t*)(Ps + r0l * SV + pc + ni * 8)       = pp[ni][0];
                *(uint32_t*)(Ps + (r0l + 8) * SV + pc + ni * 8) = pp[ni][1];
            }
        }

        CP_WAIT1();             // V(t) resident (K(t+2) may pend)
        __syncthreads();                                   // sync #2 (P + V visible)

        // ---- l update (single writer per row)
        if (wn == 0 && (lane & 3) == 0) {
            s_l[rq][r0l]     = s_l[rp][r0l]     * s_alpha[r0l]
                               + s_sum[0][r0l]     + s_sum[1][r0l];
            s_l[rq][r0l + 8] = s_l[rp][r0l + 8] * s_alpha[r0l + 8]
                               + s_sum[0][r0l + 8] + s_sum[1][r0l + 8];
        }

        // ---- rescale dacc by per-row alpha (PV rows)
        float a00 = s_alpha[pr0],      a01 = s_alpha[pr0 + 8];
        float a10 = s_alpha[pr0 + 16], a11 = s_alpha[pr0 + 24];
        #pragma unroll
        for (int ni = 0; ni < 8; ++ni) {
            dacc[0][ni][0] *= a00; dacc[0][ni][1] *= a00;
            dacc[0][ni][2] *= a01; dacc[0][ni][3] *= a01;
            dacc[1][ni][0] *= a10; dacc[1][ni][1] *= a10;
            dacc[1][ni][2] *= a11; dacc[1][ni][3] *= a11;
        }

        // ---- D += P(t) @ V(t)^T : warp tile 32 x 64 (2 mi x 8 ni), k = 64
        #pragma unroll
        for (int ks = 0; ks < 4; ++ks) {
            uint32_t af[2][4];
            #pragma unroll
            for (int mi = 0; mi < 2; ++mi)
                ldsm4(af[mi], smem_u32(Ps + (aP_row + mi * 16) * SV + ks * 16 + aA_koff));
            uint32_t bf[4][4];
            #pragma unroll
            for (int nh = 0; nh < 4; ++nh)
                ldsm4(bf[nh], smem_u32(Vs + (bV_row + nh * 16) * SV + ks * 16 + b_koff));
            #pragma unroll
            for (int mi = 0; mi < 2; ++mi)
                #pragma unroll
                for (int ni = 0; ni < 8; ++ni)
                    mma16816(dacc[mi][ni], af[mi],
                             bf[ni >> 1][(ni & 1) * 2], bf[ni >> 1][(ni & 1) * 2 + 1]);
        }
        __syncthreads();                                   // sync #3 (V, P consumed)

        load_V(Vg, Vs, ((t + 1) & (NSTEP - 1)) * BN, tid); // V(t+1)
    }

    // ---- epilogue: out = x + D / l   (final l is in s_l[0]; NSTEP even)
    float inv00 = 1.f / s_l[0][pr0];
    float inv01 = 1.f / s_l[0][pr0 + 8];
    float inv10 = 1.f / s_l[0][pr0 + 16];
    float inv11 = 1.f / s_l[0][pr0 + 24];
    #pragma unroll
    for (int mi = 0; mi < 2; ++mi) {
        float iv0 = mi ? inv10 : inv00;
        float iv1 = mi ? inv11 : inv01;
        int gi = i0 + pr0 + mi * 16;
        #pragma unroll
        for (int ni = 0; ni < 8; ++ni) {
            int c = pn * 64 + ni * 8 + (lane & 3) * 2;
            size_t a0 = ((size_t)b * Cc + c) * Nn + gi;
            size_t a1 = a0 + Nn;
            out[a0]     = x[a0]     + dacc[mi][ni][0] * iv0;
            out[a1]     = x[a1]     + dacc[mi][ni][1] * iv0;
            out[a0 + 8] = x[a0 + 8] + dacc[mi][ni][2] * iv1;
            out[a1 + 8] = x[a1 + 8] + dacc[mi][ni][3] * iv1;
        }
    }
}

// ---------------------------------------------------------------------------
extern "C" void kernel_launch(void* const* d_in, const int* in_sizes, int n_in,
                              void* d_out, int out_size)
{
    const float* x  = (const float*)d_in[0];
    const float* Wq = (const float*)d_in[1];
    const float* bq = (const float*)d_in[2];
    const float* Wk = (const float*)d_in[3];
    const float* bk = (const float*)d_in[4];
    const float* Wv = (const float*)d_in[5];
    const float* bv = (const float*)d_in[6];
    float* out = (float*)d_out;

    cudaFuncSetAttribute(flash_kernel,
                         cudaFuncAttributeMaxDynamicSharedMemorySize, SMEM_BYTES);

    wconv_kernel<<<dim3(64, 3), 256>>>(Wq, Wk, Wv);
    xpose_kernel<<<dim3(Nn / 32, Cc / 32, Bz), 256>>>(x);
    qkv_mma<<<dim3(Nn / 128, Cc / 128, Bz * 3), 256>>>(bq, bk, bv);
    flash_kernel<<<dim3(Nn / BM, Bz), 256, SMEM_BYTES>>>(x, out);
}

// round 10
// speedup vs baseline: 1.4753x; 1.0986x over previous
#include <cuda_runtime.h>
#include <cuda_bf16.h>
#include <cstdint>
#include <math.h>

#define Bz 4
#define Cc 256
#define Nn 4096
#define BM 64
#define BN 64
#define NSTEP (Nn / BN)   // 64

// ---------------- device scratch -------------------------------------------
__device__ __nv_bfloat16 g_Qt[(size_t)Bz * Nn * Cc];  // Q^T  [b][i][c]
__device__ __nv_bfloat16 g_Kt[(size_t)Bz * Nn * Cc];  // K^T  [b][j][c]
__device__ __nv_bfloat16 g_Vb[(size_t)Bz * Cc * Nn];  // V    [b][c][j]
__device__ __nv_bfloat16 g_Xt[(size_t)Bz * Nn * Cc];  // x^T  [b][n][c] bf16
__device__ __nv_bfloat16 g_Wb[3 * Cc * Cc];           // W bf16 [m][o][c]

// ---------------- PTX helpers (plain sm_103-safe) ---------------------------
__device__ __forceinline__ uint32_t smem_u32(const void* p) {
    uint32_t a;
    asm("{ .reg .u64 t; cvta.to.shared.u64 t, %1; cvt.u32.u64 %0, t; }"
        : "=r"(a) : "l"(p));
    return a;
}
__device__ __forceinline__ void ldsm4(uint32_t* r, uint32_t a) {
    asm volatile("ldmatrix.sync.aligned.m8n8.x4.shared.b16 {%0,%1,%2,%3}, [%4];"
                 : "=r"(r[0]), "=r"(r[1]), "=r"(r[2]), "=r"(r[3]) : "r"(a));
}
__device__ __forceinline__ void mma16816(float* c, const uint32_t* a,
                                         uint32_t b0, uint32_t b1) {
    asm volatile(
        "mma.sync.aligned.m16n8k16.row.col.f32.bf16.bf16.f32 "
        "{%0,%1,%2,%3}, {%4,%5,%6,%7}, {%8,%9}, {%0,%1,%2,%3};"
        : "+f"(c[0]), "+f"(c[1]), "+f"(c[2]), "+f"(c[3])
        : "r"(a[0]), "r"(a[1]), "r"(a[2]), "r"(a[3]), "r"(b0), "r"(b1));
}
#define CP_ASYNC16(dst, src) \
    asm volatile("cp.async.cg.shared.global [%0], [%1], 16;" :: "r"(dst), "l"(src))
#define CP_COMMIT() asm volatile("cp.async.commit_group;" ::: "memory")
#define CP_WAIT1()  asm volatile("cp.async.wait_group 1;" ::: "memory")
#define CP_WAIT0()  asm volatile("cp.async.wait_group 0;" ::: "memory")

// flash smem byte offsets (swizzled, no padding)
#define OFFB_Q 0          // 64 x 256 bf16 = 32768 B (512B rows, 32 chunks)
#define OFFB_K 32768      // 64 x 256 bf16 = 32768 B
#define OFFB_V 65536      // 256 x 64 bf16 = 32768 B (128B rows, 8 chunks)
#define OFFB_P 98304      // 64 x 64 bf16  = 8192 B
#define SMEM_BYTES 106496

// ---------------------------------------------------------------------------
// Prep A: W fp32 -> bf16
// ---------------------------------------------------------------------------
__global__ __launch_bounds__(256) void wconv_kernel(
    const float* __restrict__ Wq, const float* __restrict__ Wk,
    const float* __restrict__ Wv)
{
    int m = blockIdx.y;
    const float* W = (m == 0) ? Wq : (m == 1) ? Wk : Wv;
    int idx = (blockIdx.x * 256 + threadIdx.x) * 4;
    float4 v = *(const float4*)&W[idx];
    __nv_bfloat162 p[2];
    p[0] = __floats2bfloat162_rn(v.x, v.y);
    p[1] = __floats2bfloat162_rn(v.z, v.w);
    *(uint2*)&g_Wb[m * Cc * Cc + idx] = *(uint2*)p;
}

// ---------------------------------------------------------------------------
// Prep B: transpose-convert x [b][c][n] fp32 -> Xt [b][n][c] bf16
// ---------------------------------------------------------------------------
__global__ __launch_bounds__(256) void xpose_kernel(const float* __restrict__ x)
{
    __shared__ float tile[32][33];
    int b = blockIdx.z;
    int c0 = blockIdx.y * 32, n0 = blockIdx.x * 32;
    int tx = threadIdx.x & 31, ty = threadIdx.x >> 5;
    #pragma unroll
    for (int s = 0; s < 4; ++s)
        tile[ty + s * 8][tx] = x[((size_t)b * Cc + c0 + ty + s * 8) * Nn + n0 + tx];
    __syncthreads();
    #pragma unroll
    for (int s = 0; s < 4; ++s)
        g_Xt[((size_t)b * Nn + n0 + ty + s * 8) * Cc + c0 + tx] =
            __float2bfloat16(tile[tx][ty + s * 8]);
}

// ---------------------------------------------------------------------------
// Shared HMMA GEMM core (validated): C[128x128] = A[128xK] B[128xK]^T
// ---------------------------------------------------------------------------
#define LDS 40

template<int LDGA, int LDGB, int KT>
__device__ __forceinline__ void gemm_bf16(
    const __nv_bfloat16* __restrict__ Ag,
    const __nv_bfloat16* __restrict__ Bg,
    float acc[4][4][4])
{
    __shared__ alignas(16) __nv_bfloat16 Asm[2][128 * LDS];
    __shared__ alignas(16) __nv_bfloat16 Bsm[2][128 * LDS];

    const int tid = threadIdx.x;
    const int lane = tid & 31, wid = tid >> 5;
    const int wm = wid & 1, wn = wid >> 1;
    const int r0 = tid >> 2, cb = tid & 3;

    auto load_tile = [&](int s, int kt) {
        int k0 = kt * 32;
        #pragma unroll
        for (int h = 0; h < 2; ++h) {
            int r = r0 + h * 64;
            CP_ASYNC16(smem_u32(&Asm[s][r * LDS + cb * 8]),
                       Ag + (size_t)r * LDGA + k0 + cb * 8);
            CP_ASYNC16(smem_u32(&Bsm[s][r * LDS + cb * 8]),
                       Bg + (size_t)r * LDGB + k0 + cb * 8);
        }
        CP_COMMIT();
    };

    const int a_row = wm * 64 + (lane & 15);
    const int a_koff = (lane >> 4) * 8;
    const int b_row = wn * 32 + (lane & 7) + ((lane >> 4) << 3);
    const int b_koff = ((lane >> 3) & 1) * 8;

    load_tile(0, 0);

    #pragma unroll 1
    for (int kt = 0; kt < KT; ++kt) {
        if (kt + 1 < KT) {
            load_tile((kt + 1) & 1, kt + 1);
            CP_WAIT1();
        } else {
            CP_WAIT0();
        }
        __syncthreads();

        const __nv_bfloat16* as = &Asm[kt & 1][0];
        const __nv_bfloat16* bs = &Bsm[kt & 1][0];

        #pragma unroll
        for (int ks = 0; ks < 2; ++ks) {
            int k0 = ks * 16;
            uint32_t af[4][4], bf[2][4];
            #pragma unroll
            for (int mi = 0; mi < 4; ++mi)
                ldsm4(af[mi], smem_u32(as + (a_row + mi * 16) * LDS + k0 + a_koff));
            #pragma unroll
            for (int nh = 0; nh < 2; ++nh)
                ldsm4(bf[nh], smem_u32(bs + (b_row + nh * 16) * LDS + k0 + b_koff));
            #pragma unroll
            for (int mi = 0; mi < 4; ++mi)
                #pragma unroll
                for (int ni = 0; ni < 4; ++ni)
                    mma16816(acc[mi][ni], af[mi],
                             bf[ni >> 1][(ni & 1) * 2], bf[ni >> 1][(ni & 1) * 2 + 1]);
        }
        __syncthreads();
    }
}

// ---------------------------------------------------------------------------
// QKV via HMMA (validated)
// ---------------------------------------------------------------------------
__global__ __launch_bounds__(256) void qkv_mma(
    const float* __restrict__ bq, const float* __restrict__ bk,
    const float* __restrict__ bv)
{
    int m = blockIdx.z % 3;
    int b = blockIdx.z / 3;
    const float* bias = (m == 0) ? bq : (m == 1) ? bk : bv;
    int n0 = blockIdx.x * 128;
    int o0 = blockIdx.y * 128;

    const __nv_bfloat16* Xt = g_Xt + (size_t)b * Nn * Cc + (size_t)n0 * Cc;
    const __nv_bfloat16* Wm = g_Wb + (size_t)m * Cc * Cc + (size_t)o0 * Cc;

    float acc[4][4][4] = {};
    if (m < 2) gemm_bf16<Cc, Cc, Cc / 32>(Xt, Wm, acc);
    else       gemm_bf16<Cc, Cc, Cc / 32>(Wm, Xt, acc);

    int lane = threadIdx.x & 31, wid = threadIdx.x >> 5;
    int wm = wid & 1, wn = wid >> 1;

    if (m < 2) {
        __nv_bfloat16* T = ((m == 0) ? g_Qt : g_Kt) + (size_t)b * Nn * Cc;
        #pragma unroll
        for (int mi = 0; mi < 4; ++mi) {
            int row = n0 + wm * 64 + mi * 16 + (lane >> 2);
            #pragma unroll
            for (int ni = 0; ni < 4; ++ni) {
                int col = o0 + wn * 32 + ni * 8 + (lane & 3) * 2;
                float b0v = bias[col], b1v = bias[col + 1];
                __nv_bfloat162 p0 = __floats2bfloat162_rn(acc[mi][ni][0] + b0v,
                                                          acc[mi][ni][1] + b1v);
                __nv_bfloat162 p1 = __floats2bfloat162_rn(acc[mi][ni][2] + b0v,
                                                          acc[mi][ni][3] + b1v);
                *(uint32_t*)&T[(size_t)row * Cc + col]       = *(uint32_t*)&p0;
                *(uint32_t*)&T[(size_t)(row + 8) * Cc + col] = *(uint32_t*)&p1;
            }
        }
    } else {
        __nv_bfloat16* Vb = g_Vb + (size_t)b * Cc * Nn;
        #pragma unroll
        for (int mi = 0; mi < 4; ++mi) {
            int row = o0 + wm * 64 + mi * 16 + (lane >> 2);
            float b0v = bias[row], b1v = bias[row + 8];
            #pragma unroll
            for (int ni = 0; ni < 4; ++ni) {
                int col = n0 + wn * 32 + ni * 8 + (lane & 3) * 2;
                __nv_bfloat162 p0 = __floats2bfloat162_rn(acc[mi][ni][0] + b0v,
                                                          acc[mi][ni][1] + b0v);
                __nv_bfloat162 p1 = __floats2bfloat162_rn(acc[mi][ni][2] + b1v,
                                                          acc[mi][ni][3] + b1v);
                *(uint32_t*)&Vb[(size_t)row * Nn + col]       = *(uint32_t*)&p0;
                *(uint32_t*)&Vb[(size_t)(row + 8) * Nn + col] = *(uint32_t*)&p1;
            }
        }
    }
}

// ---------------------------------------------------------------------------
// Fused flash attention: 256 threads, 8 warps, 2 CTAs/SM.
// Swizzled no-pad smem; single K / single V buffer; 3 syncs/step.
// S layout 4m x 2n, PV layout 2m' x 4n'.
// ---------------------------------------------------------------------------
__global__ __launch_bounds__(256, 2) void flash_kernel(
    const float* __restrict__ x, float* __restrict__ out)
{
    extern __shared__ __nv_bfloat16 sm[];
    __shared__ float s_mx[2][64], s_sum[2][64];
    __shared__ float s_m[2][64], s_l[2][64], s_alpha[64];

    char* smb = (char*)sm;
    const uint32_t uS = smem_u32(sm);
    const uint32_t uQ = uS + OFFB_Q;
    const uint32_t uK = uS + OFFB_K;
    const uint32_t uV = uS + OFFB_V;
    const uint32_t uP = uS + OFFB_P;

    const int tid = threadIdx.x;
    const int lane = tid & 31, wid = tid >> 5;
    const int wm = wid & 3, wn = wid >> 2;      // S: 4m x 2n
    const int pm = wid & 1, pn = wid >> 1;      // PV: 2m' x 4n'
    const int b = blockIdx.y;
    const int i0 = blockIdx.x * BM;

    const __nv_bfloat16* Qg = g_Qt + (size_t)b * Nn * Cc + (size_t)i0 * Cc;
    const __nv_bfloat16* Kg = g_Kt + (size_t)b * Nn * Cc;
    const __nv_bfloat16* Vg = g_Vb + (size_t)b * Cc * Nn;

    if (tid < 64) { s_m[0][tid] = -1e30f; s_l[0][tid] = 0.f; }

    // ---- loaders (16B chunk swizzle: c16 ^= row & 7)
    auto putQK = [&](uint32_t dst, const __nv_bfloat16* src) {   // 64 x 256
        #pragma unroll
        for (int h = 0; h < 8; ++h) {
            int q = tid + h * 256;
            int r = q >> 5, c = q & 31;
            CP_ASYNC16(dst + (uint32_t)((r * 32 + (c ^ (r & 7))) * 16),
                       src + (size_t)r * Cc + c * 8);
        }
    };
    auto putV = [&](int j0) {                                     // 256 x 64
        #pragma unroll
        for (int h = 0; h < 8; ++h) {
            int q = tid + h * 256;
            int r = q >> 3, c = q & 7;
            CP_ASYNC16(uV + (uint32_t)((r * 8 + (c ^ (r & 7))) * 16),
                       Vg + (size_t)r * Nn + j0 + c * 8);
        }
        CP_COMMIT();
    };

    // prologue: G1 = {Q, K(0)}, G2 = {V(0)}
    putQK(uQ, Qg);
    putQK(uK, Kg);
    CP_COMMIT();
    putV(0);
    CP_WAIT1();          // G1 done (G2 may pend)
    __syncthreads();

    // ---- ldsm addressing (row & 7 == lane-derived constants)
    const int kx = lane & 7;
    const uint32_t qa_base = uQ + (uint32_t)((wm * 16 + (lane & 15)) * 512);
    const int qhi = (lane >> 4) & 1;
    const uint32_t kb_base = uK + (uint32_t)((wn * 32 + (lane & 7) + ((lane >> 4) << 3)) * 512);
    const int khi = (lane >> 3) & 1;
    const int r0l = wm * 16 + (lane >> 2);
    const int px = lane >> 2;                       // r0l & 7
    const uint32_t pa_base = uP + (uint32_t)((pm * 32 + (lane & 15)) * 128);
    const uint32_t vb_base = uV + (uint32_t)((pn * 64 + (lane & 7) + ((lane >> 4) << 3)) * 128);
    const int pr0 = pm * 32 + (lane >> 2);
    char* pst0 = smb + OFFB_P + r0l * 128 + (lane & 3) * 4;

    float dacc[2][8][4] = {};

    #pragma unroll 1
    for (int t = 0; t < NSTEP; ++t) {
        // ---- S(t) = Q @ K(t)^T : warp tile 16 x 32
        float sacc[4][4] = {};
        #pragma unroll
        for (int ks = 0; ks < 16; ++ks) {
            uint32_t af[4];
            ldsm4(af, qa_base + (uint32_t)((((2 * ks + qhi) ^ kx)) << 4));
            uint32_t bf[2][4];
            #pragma unroll
            for (int nh = 0; nh < 2; ++nh)
                ldsm4(bf[nh], kb_base + (uint32_t)(nh * 8192 + ((((2 * ks + khi) ^ kx)) << 4)));
            #pragma unroll
            for (int ni = 0; ni < 4; ++ni)
                mma16816(sacc[ni], af, bf[ni >> 1][(ni & 1) * 2],
                         bf[ni >> 1][(ni & 1) * 2 + 1]);
        }

        // ---- row max partials
        float tmx0 = -1e30f, tmx1 = -1e30f;
        #pragma unroll
        for (int ni = 0; ni < 4; ++ni) {
            sacc[ni][0] *= 0.0625f; sacc[ni][1] *= 0.0625f;
            sacc[ni][2] *= 0.0625f; sacc[ni][3] *= 0.0625f;
            tmx0 = fmaxf(tmx0, fmaxf(sacc[ni][0], sacc[ni][1]));
            tmx1 = fmaxf(tmx1, fmaxf(sacc[ni][2], sacc[ni][3]));
        }
        tmx0 = fmaxf(tmx0, __shfl_xor_sync(0xffffffffu, tmx0, 1));
        tmx0 = fmaxf(tmx0, __shfl_xor_sync(0xffffffffu, tmx0, 2));
        tmx1 = fmaxf(tmx1, __shfl_xor_sync(0xffffffffu, tmx1, 1));
        tmx1 = fmaxf(tmx1, __shfl_xor_sync(0xffffffffu, tmx1, 2));
        if ((lane & 3) == 0) {
            s_mx[wn][r0l]     = tmx0;
            s_mx[wn][r0l + 8] = tmx1;
        }
        __syncthreads();                                   // sync #1 (K consumed)

        // K buffer free -> issue K(t+1)
        putQK(uK, Kg + (size_t)(((t + 1) & (NSTEP - 1)) * BN) * Cc);
        CP_COMMIT();

        // ---- softmax
        const int rp = t & 1, rq = rp ^ 1;
        float mo0 = s_m[rp][r0l], mo1 = s_m[rp][r0l + 8];
        float mn0 = fmaxf(mo0, fmaxf(s_mx[0][r0l],     s_mx[1][r0l]));
        float mn1 = fmaxf(mo1, fmaxf(s_mx[0][r0l + 8], s_mx[1][r0l + 8]));
        float al0 = __expf(mo0 - mn0);
        float al1 = __expf(mo1 - mn1);
        if (wn == 0 && (lane & 3) == 0) {
            s_m[rq][r0l] = mn0;  s_m[rq][r0l + 8] = mn1;
            s_alpha[r0l] = al0;  s_alpha[r0l + 8] = al1;
        }

        float ts0 = 0.f, ts1 = 0.f;
        #pragma unroll
        for (int ni = 0; ni < 4; ++ni) {
            float p0 = __expf(sacc[ni][0] - mn0);
            float p1 = __expf(sacc[ni][1] - mn0);
            float p2 = __expf(sacc[ni][2] - mn1);
            float p3 = __expf(sacc[ni][3] - mn1);
            ts0 += p0 + p1; ts1 += p2 + p3;
            __nv_bfloat162 q0 = __floats2bfloat162_rn(p0, p1);
            __nv_bfloat162 q1 = __floats2bfloat162_rn(p2, p3);
            int cxa = ((wn * 4 + ni) ^ px) * 16;
            *(uint32_t*)(pst0 + cxa)        = *(uint32_t*)&q0;
            *(uint32_t*)(pst0 + 1024 + cxa) = *(uint32_t*)&q1;   // row +8 (8*128)
        }
        ts0 += __shfl_xor_sync(0xffffffffu, ts0, 1);
        ts0 += __shfl_xor_sync(0xffffffffu, ts0, 2);
        ts1 += __shfl_xor_sync(0xffffffffu, ts1, 1);
        ts1 += __shfl_xor_sync(0xffffffffu, ts1, 2);
        if ((lane & 3) == 0) {
            s_sum[wn][r0l]     = ts0;
            s_sum[wn][r0l + 8] = ts1;
        }

        CP_WAIT1();             // V(t) resident (K(t+1) may pend)
        __syncthreads();                                   // sync #2 (P + V visible)

        // ---- l update
        if (wn == 0 && (lane & 3) == 0) {
            s_l[rq][r0l]     = s_l[rp][r0l]     * s_alpha[r0l]
                               + s_sum[0][r0l]     + s_sum[1][r0l];
            s_l[rq][r0l + 8] = s_l[rp][r0l + 8] * s_alpha[r0l + 8]
                               + s_sum[0][r0l + 8] + s_sum[1][r0l + 8];
        }

        // ---- rescale dacc (PV rows)
        float a00 = s_alpha[pr0],      a01 = s_alpha[pr0 + 8];
        float a10 = s_alpha[pr0 + 16], a11 = s_alpha[pr0 + 24];
        #pragma unroll
        for (int ni = 0; ni < 8; ++ni) {
            dacc[0][ni][0] *= a00; dacc[0][ni][1] *= a00;
            dacc[0][ni][2] *= a01; dacc[0][ni][3] *= a01;
            dacc[1][ni][0] *= a10; dacc[1][ni][1] *= a10;
            dacc[1][ni][2] *= a11; dacc[1][ni][3] *= a11;
        }

        // ---- D += P(t) @ V(t)^T : warp tile 32 x 64 (2 mi x 8 ni), k = 64
        #pragma unroll
        for (int ks = 0; ks < 4; ++ks) {
            uint32_t af[2][4];
            #pragma unroll
            for (int mi = 0; mi < 2; ++mi)
                ldsm4(af[mi], pa_base + (uint32_t)(mi * 2048 +
                          ((((2 * ks + qhi) ^ kx)) << 4)));
            uint32_t bf[4][4];
            #pragma unroll
            for (int nh = 0; nh < 4; ++nh)
                ldsm4(bf[nh], vb_base + (uint32_t)(nh * 2048 +
                          ((((2 * ks + khi) ^ kx)) << 4)));
            #pragma unroll
            for (int mi = 0; mi < 2; ++mi)
                #pragma unroll
                for (int ni = 0; ni < 8; ++ni)
                    mma16816(dacc[mi][ni], af[mi],
                             bf[ni >> 1][(ni & 1) * 2], bf[ni >> 1][(ni & 1) * 2 + 1]);
        }

        CP_WAIT0();             // K(t+1) done too
        __syncthreads();                                   // sync #3 (all consumed)

        putV(((t + 1) & (NSTEP - 1)) * BN);                // V(t+1)
    }

    // ---- epilogue: out = x + D / l  (final l in s_l[0]; NSTEP even)
    float inv00 = 1.f / s_l[0][pr0];
    float inv01 = 1.f / s_l[0][pr0 + 8];
    float inv10 = 1.f / s_l[0][pr0 + 16];
    float inv11 = 1.f / s_l[0][pr0 + 24];
    #pragma unroll
    for (int mi = 0; mi < 2; ++mi) {
        float iv0 = mi ? inv10 : inv00;
        float iv1 = mi ? inv11 : inv01;
        int gi = i0 + pr0 + mi * 16;
        #pragma unroll
        for (int ni = 0; ni < 8; ++ni) {
            int c = pn * 64 + ni * 8 + (lane & 3) * 2;
            size_t a0 = ((size_t)b * Cc + c) * Nn + gi;
            size_t a1 = a0 + Nn;
            out[a0]     = x[a0]     + dacc[mi][ni][0] * iv0;
            out[a1]     = x[a1]     + dacc[mi][ni][1] * iv0;
            out[a0 + 8] = x[a0 + 8] + dacc[mi][ni][2] * iv1;
            out[a1 + 8] = x[a1 + 8] + dacc[mi][ni][3] * iv1;
        }
    }
}

// ---------------------------------------------------------------------------
extern "C" void kernel_launch(void* const* d_in, const int* in_sizes, int n_in,
                              void* d_out, int out_size)
{
    const float* x  = (const float*)d_in[0];
    const float* Wq = (const float*)d_in[1];
    const float* bq = (const float*)d_in[2];
    const float* Wk = (const float*)d_in[3];
    const float* bk = (const float*)d_in[4];
    const float* Wv = (const float*)d_in[5];
    const float* bv = (const float*)d_in[6];
    float* out = (float*)d_out;

    cudaFuncSetAttribute(flash_kernel,
                         cudaFuncAttributeMaxDynamicSharedMemorySize, SMEM_BYTES);

    wconv_kernel<<<dim3(64, 3), 256>>>(Wq, Wk, Wv);
    xpose_kernel<<<dim3(Nn / 32, Cc / 32, Bz), 256>>>(x);
    qkv_mma<<<dim3(Nn / 128, Cc / 128, Bz * 3), 256>>>(bq, bk, bv);
    flash_kernel<<<dim3(Nn / BM, Bz), 256, SMEM_BYTES>>>(x, out);
}